// round 16
// baseline (speedup 1.0000x reference)
#include <cuda_runtime.h>
#include <cuda_bf16.h>
#include <cuda_fp16.h>
#include <cstdint>

#define BB   4
#define NQ   512
#define NK   512
#define DD   512
#define HH   128

#define TQ   8
#define TK   32

// ---------------- scratch (allocation-free device globals) ----------------
__device__ float  g_Qp[BB * NQ * HH];
__device__ float  g_Kp[BB * NK * HH];
__device__ __half g_Qf[BB * NQ * DD];
__device__ __half g_Kf[BB * NK * DD];
__device__ __half g_Wqt[HH * DD];            // W^T [128][512]
__device__ __half g_Wkt[HH * DD];
__device__ __half g_Vt[BB * DD * NK];        // V^T per batch [n][k]
__device__ __half g_Pf[BB * NQ * NK];

__device__ __forceinline__ __half2 tanh2(__half2 x) {
    __half2 y;
    asm("tanh.approx.f16x2 %0, %1;" : "=r"(*(uint32_t*)&y) : "r"(*(const uint32_t*)&x));
    return y;
}

__device__ __forceinline__ long long read_vlen(const void* p, int b) {
    const int* w = (const int*)p;
    bool is64 = (w[1] == 0) && (w[3] == 0);
    if (is64) return ((const long long*)p)[b];
    return (long long)w[b];
}

__device__ __forceinline__ uint32_t smem_u32(const void* p) {
    uint32_t a;
    asm("{ .reg .u64 t; cvta.to.shared.u64 t, %1; cvt.u32.u64 %0, t; }" : "=r"(a) : "l"(p));
    return a;
}

__device__ __forceinline__ void ldmx4(uint32_t* r, uint32_t addr) {
    asm volatile("ldmatrix.sync.aligned.m8n8.x4.shared.b16 {%0,%1,%2,%3}, [%4];"
        : "=r"(r[0]), "=r"(r[1]), "=r"(r[2]), "=r"(r[3]) : "r"(addr));
}

__device__ __forceinline__ void mma16816h(float* d, const uint32_t* a, const uint32_t* b) {
    asm volatile("mma.sync.aligned.m16n8k16.row.col.f32.f16.f16.f32 "
        "{%0,%1,%2,%3}, {%4,%5,%6,%7}, {%8,%9}, {%0,%1,%2,%3};"
        : "+f"(d[0]), "+f"(d[1]), "+f"(d[2]), "+f"(d[3])
        : "r"(a[0]), "r"(a[1]), "r"(a[2]), "r"(a[3]), "r"(b[0]), "r"(b[1]));
}

__device__ __forceinline__ void cpa16(uint32_t dst, const void* src) {
    asm volatile("cp.async.cg.shared.global [%0], [%1], 16;" :: "r"(dst), "l"(src));
}
#define CP_COMMIT() asm volatile("cp.async.commit_group;" ::: "memory")

// ---------------- merged prep kernel (fp16 convert + transposes) ----------
__global__ __launch_bounds__(256)
void prep(const float* __restrict__ Q, const float* __restrict__ K,
          const float* __restrict__ V, const float* __restrict__ Wq,
          const float* __restrict__ Wk, const void* __restrict__ vlen)
{
    __shared__ float t[32][33];
    const int tid = threadIdx.x;
    const int bid = blockIdx.x;

    if (bid < 2048) {
        const bool isK = bid >= 1024;
        const float* in = isK ? K : Q;
        __half* o = isK ? g_Kf : g_Qf;
        int i = (bid & 1023) * 256 + tid;
        float4 v = ((const float4*)in)[i];
        ((__half2*)o)[i * 2 + 0] = __floats2half2_rn(v.x, v.y);
        ((__half2*)o)[i * 2 + 1] = __floats2half2_rn(v.z, v.w);
    } else if (bid < 2560) {
        const int r = bid - 2048;
        const bool isK = r >= 256;
        const float* W = isK ? Wk : Wq;
        __half* th = isK ? g_Wkt : g_Wqt;
        int i = (r & 255) * 256 + tid;
        int k = i >> 7, n = i & 127;
        th[n * DD + k] = __float2half(W[i]);
    } else {
        const int r  = bid - 2560;
        const int b  = r >> 8;
        const int ky = (r & 255) >> 4;
        const int nx = r & 15;
        const int k0 = ky * 32;
        if ((long long)k0 >= read_vlen(vlen, b)) return;
        const int n0 = nx * 32;
        const int tx = tid & 31, ty = tid >> 5;
        const float* Vb = V + (long long)b * NK * DD;
#pragma unroll
        for (int rr = 0; rr < 4; rr++)
            t[ty + rr * 8][tx] = Vb[(long long)(k0 + ty + rr * 8) * DD + n0 + tx];
        __syncthreads();
        __half* th = g_Vt + (long long)b * DD * NK;
#pragma unroll
        for (int rr = 0; rr < 4; rr++)
            th[(long long)(n0 + ty + rr * 8) * NK + k0 + tx] = __float2half(t[tx][ty + rr * 8]);
    }
}

// ---------------- warp-MMA fp16 GEMM: C[128x64] = A[128xK] @ B[64xK]^T ----
// 256 threads = 8 warps (4m x 2n), warp tile 32x32. 80B-padded rows.
// 4-stage cp.async ring (60KB dynamic smem) -> 2 CTAs/SM.
#define O_A   0
#define O_B   10240
#define STG   15360
#define NSTG  4
#define MMA_DSMEM (NSTG * STG)

__device__ __forceinline__ void mma_gemm(
    const __half* __restrict__ A, const __half* __restrict__ B,
    float* __restrict__ C, int lda, int ldb, int ldc,
    int m0, int n0, int nstages)
{
    extern __shared__ __align__(128) char smem[];
    const uint32_t sb = smem_u32(smem);
    const int tid  = threadIdx.x;
    const int lane = tid & 31;
    const int w    = tid >> 5;
    const int wm   = w & 3;     // 32-row slice
    const int wn   = w >> 2;    // 32-col slice

    const int lrow = tid >> 2;             // 0..63
    const int lchk = tid & 3;
    const __half* pA = A + (long long)(m0 + lrow) * lda + lchk * 8;
    const __half* pB = B + (long long)(n0 + lrow) * ldb + lchk * 8;
    const long long a64 = 64LL * lda;
    const uint32_t stO = lrow * 80 + lchk * 16;

    const uint32_t aOff = (wm * 32 + (lane & 15)) * 80 + (lane >> 4) * 16;
    const int jj = lane >> 3;
    const uint32_t bOff = (wn * 32 + (jj >> 1) * 8 + (lane & 7)) * 80 + (jj & 1) * 16;

    float acc[8][4] = {};

#pragma unroll
    for (int s = 0; s < NSTG - 1; s++) {
        if (s < nstages) {
            uint32_t d = sb + s * STG;
            cpa16(d + O_A + stO,        pA + s * 32);
            cpa16(d + O_A + stO + 5120, pA + s * 32 + a64);
            cpa16(d + O_B + stO,        pB + s * 32);
        }
        CP_COMMIT();
    }

    for (int t = 0; t < nstages; t++) {
        asm volatile("cp.async.wait_group %0;" :: "n"(NSTG - 2) : "memory");
        __syncthreads();

        {
            int s = t + NSTG - 1;
            if (s < nstages) {
                uint32_t d = sb + (uint32_t)(s & (NSTG - 1)) * STG;
                cpa16(d + O_A + stO,        pA + s * 32);
                cpa16(d + O_A + stO + 5120, pA + s * 32 + a64);
                cpa16(d + O_B + stO,        pB + s * 32);
            }
            CP_COMMIT();
        }

        const uint32_t cur = sb + (uint32_t)(t & (NSTG - 1)) * STG;
#pragma unroll
        for (int ks = 0; ks < 2; ks++) {
            uint32_t a[2][4];
            ldmx4(a[0], cur + O_A + aOff + ks * 32);
            ldmx4(a[1], cur + O_A + aOff + 1280 + ks * 32);
#pragma unroll
            for (int np = 0; np < 2; np++) {
                uint32_t b[4];
                ldmx4(b, cur + O_B + bOff + np * 1280 + ks * 32);
#pragma unroll
                for (int ms = 0; ms < 2; ms++) {
                    mma16816h(acc[ms * 4 + 2 * np + 0], a[ms], b);
                    mma16816h(acc[ms * 4 + 2 * np + 1], a[ms], b + 2);
                }
            }
        }
    }

#pragma unroll
    for (int ms = 0; ms < 2; ms++) {
        const int rr = m0 + wm * 32 + ms * 16 + (lane >> 2);
        const int cc = n0 + wn * 32 + (lane & 3) * 2;
#pragma unroll
        for (int nt = 0; nt < 4; nt++) {
            float* a = acc[ms * 4 + nt];
            *(float2*)&C[(long long)rr * ldc + cc + nt * 8]       = make_float2(a[0], a[1]);
            *(float2*)&C[(long long)(rr + 8) * ldc + cc + nt * 8] = make_float2(a[2], a[3]);
        }
    }
}

// z=0: Qp = Q@Wq; z=1: Kp = K@Wk (skip fully-masked 128-row blocks)
__global__ __launch_bounds__(256, 2)
void mma_proj(const void* __restrict__ vlen)
{
    const int n0 = blockIdx.x * 64;
    const int m0 = blockIdx.y * 128;
    if (blockIdx.z == 0) {
        mma_gemm(g_Qf, g_Wqt, g_Qp, DD, DD, HH, m0, n0, DD / 32);
    } else {
        if ((long long)(m0 & (NK - 1)) >= read_vlen(vlen, m0 >> 9)) return;
        mma_gemm(g_Kf, g_Wkt, g_Kp, DD, DD, HH, m0, n0, DD / 32);
    }
}

// out[b] = P[b] @ V[b]; K-loop bounded by valid length.
__global__ __launch_bounds__(256, 2)
void mma_pv(float* __restrict__ out, const void* __restrict__ vlen)
{
    const int b = blockIdx.z;
    const long long vl = read_vlen(vlen, b);
    const int ns = (int)((vl + 31) >> 5);
    mma_gemm(g_Pf + (long long)b * NQ * NK,
             g_Vt + (long long)b * DD * NK,
             out + (long long)b * NQ * DD,
             NK, NK, DD, blockIdx.y * 128, blockIdx.x * 64, ns);
}

// ---------------- fused scores + mask + softmax -> P (half2 tanh) ----------
// Row stride 66 uints (half2) per 128-h row.
#define HP2 66
__global__ __launch_bounds__(256)
void scores_softmax(const float* __restrict__ Qp, const float* __restrict__ Kp,
                    const float* __restrict__ wv, const void* __restrict__ vlen)
{
    __shared__ uint32_t qps2[TQ][HP2];
    __shared__ uint32_t kps2[2][TK][HP2];
    __shared__ uint32_t wvs2[64];
    __shared__ float s[TQ][NK];

    const int tid = threadIdx.x;
    const int bx  = blockIdx.x;
    const int b   = bx / (NQ / TQ);
    const int q0  = (bx % (NQ / TQ)) * TQ;

    const long long vl = read_vlen(vlen, b);
    const int NT = (int)((vl + TK - 1) / TK);

    if (tid < 64) {
        float2 wf = *(const float2*)&wv[tid * 2];
        __half2 h = __floats2half2_rn(wf.x, wf.y);
        wvs2[tid] = *(uint32_t*)&h;
    }

    {
        const int q   = tid >> 5;
        const int h4  = (tid & 31) * 4;
        float4 v = *(const float4*)&Qp[(long long)(b * NQ + q0 + q) * HH + h4];
        __half2 h0 = __floats2half2_rn(v.x, v.y);
        __half2 h1 = __floats2half2_rn(v.z, v.w);
        qps2[q][(tid & 31) * 2 + 0] = *(uint32_t*)&h0;
        qps2[q][(tid & 31) * 2 + 1] = *(uint32_t*)&h1;
    }

    const int q = tid >> 5;
    const int k = tid & 31;

    const float* kbase = &Kp[(long long)b * NK * HH];
    const int lrow = tid >> 5;
    const int lh4  = (tid & 31) * 4;
    const int lu   = (tid & 31) * 2;

#pragma unroll
    for (int r = 0; r < 4; r++) {
        int kk = lrow + 8 * r;
        float4 v = *(const float4*)&kbase[(long long)kk * HH + lh4];
        __half2 h0 = __floats2half2_rn(v.x, v.y);
        __half2 h1 = __floats2half2_rn(v.z, v.w);
        kps2[0][kk][lu + 0] = *(uint32_t*)&h0;
        kps2[0][kk][lu + 1] = *(uint32_t*)&h1;
    }
    __syncthreads();

    for (int kt = 0; kt < NT; kt++) {
        const int cur = kt & 1;
        const int nxt = cur ^ 1;
        float4 pre[4];
        const bool more = (kt + 1 < NT);
        if (more) {
#pragma unroll
            for (int r = 0; r < 4; r++) {
                int kk = lrow + 8 * r;
                pre[r] = *(const float4*)&kbase[(long long)((kt + 1) * TK + kk) * HH + lh4];
            }
        }

        float acc = 0.f;
#pragma unroll
        for (int hc = 0; hc < 8; hc++) {      // 8 chunks of 16 h (short fp16 chains)
            __half2 acc2 = __floats2half2_rn(0.f, 0.f);
#pragma unroll
            for (int i = 0; i < 4; i++) {     // 4 x uint2 = 16 h
                const int u = hc * 8 + i * 2;
                uint2 kv  = *(const uint2*)&kps2[cur][k][u];
                uint2 qv  = *(const uint2*)&qps2[q][u];
                uint2 wv2 = *(const uint2*)&wvs2[u];    // SAME half2 units as rows
                __half2 t0 = tanh2(__hadd2(*(__half2*)&kv.x, *(__half2*)&qv.x));
                __half2 t1 = tanh2(__hadd2(*(__half2*)&kv.y, *(__half2*)&qv.y));
                acc2 = __hfma2(t0, *(__half2*)&wv2.x, acc2);
                acc2 = __hfma2(t1, *(__half2*)&wv2.y, acc2);
            }
            float2 f = __half22float2(acc2);
            acc += f.x + f.y;
        }
        s[q][kt * TK + k] = acc;

        if (more) {
#pragma unroll
            for (int r = 0; r < 4; r++) {
                int kk = lrow + 8 * r;
                __half2 h0 = __floats2half2_rn(pre[r].x, pre[r].y);
                __half2 h1 = __floats2half2_rn(pre[r].z, pre[r].w);
                kps2[nxt][kk][lu + 0] = *(uint32_t*)&h0;
                kps2[nxt][kk][lu + 1] = *(uint32_t*)&h1;
            }
        }
        __syncthreads();
    }

    const int lane = k;
    const int kmax = NT * TK;

    float m = -1e30f;
    for (int j = lane; j < kmax; j += 32) {
        float x = (j < vl) ? s[q][j] : -1e30f;
        m = fmaxf(m, x);
    }
#pragma unroll
    for (int o = 16; o > 0; o >>= 1) m = fmaxf(m, __shfl_xor_sync(0xffffffffu, m, o));

    float sum = 0.f;
    for (int j = lane; j < kmax; j += 32) {
        float e = (j < vl) ? __expf(s[q][j] - m) : 0.f;
        s[q][j] = e;
        sum += e;
    }
#pragma unroll
    for (int o = 16; o > 0; o >>= 1) sum += __shfl_xor_sync(0xffffffffu, sum, o);

    const float inv = 1.f / sum;
    __half* pf = g_Pf + (long long)(b * NQ + q0 + q) * NK;
    for (int j = lane; j < kmax; j += 32) {
        float x = (j < vl) ? s[q][j] * inv : 0.f;
        pf[j] = __float2half(x);
    }
}

// ---------------------------------------------------------------------------
extern "C" void kernel_launch(void* const* d_in, const int* in_sizes, int n_in,
                              void* d_out, int out_size)
{
    const float* Q    = (const float*)d_in[0];
    const float* K    = (const float*)d_in[1];
    const float* V    = (const float*)d_in[2];
    const float* Wq   = (const float*)d_in[3];
    const float* Wk   = (const float*)d_in[4];
    const float* wv   = (const float*)d_in[5];
    const void*  vlen = (const void*)d_in[6];
    float*       out  = (float*)d_out;

    float *pQp, *pKp;
    cudaGetSymbolAddress((void**)&pQp, g_Qp);
    cudaGetSymbolAddress((void**)&pKp, g_Kp);

    static bool attr_done = false;
    if (!attr_done) {
        cudaFuncSetAttribute(mma_proj, cudaFuncAttributeMaxDynamicSharedMemorySize, MMA_DSMEM);
        cudaFuncSetAttribute(mma_pv,   cudaFuncAttributeMaxDynamicSharedMemorySize, MMA_DSMEM);
        attr_done = true;
    }

    // prep: fp16 converts + transposes, single launch
    prep<<<3584, 256>>>(Q, K, V, Wq, Wk, vlen);

    // projections: grid (2, 16, 2) = 64 CTAs, 128x64 tiles
    {
        dim3 g(HH / 64, (BB * NQ) / 128, 2);
        mma_proj<<<g, 256, MMA_DSMEM>>>(vlen);
    }
    // scores + mask + softmax -> P (fp16)
    {
        dim3 g(BB * NQ / TQ);
        scores_softmax<<<g, 256>>>(pQp, pKp, wv, vlen);
    }
    // out = P @ V: grid (8, 4, 4) = 128 CTAs
    {
        dim3 g(DD / 64, NQ / 128, BB);
        mma_pv<<<g, 256, MMA_DSMEM>>>(out, vlen);
    }
}

// round 17
// speedup vs baseline: 1.0350x; 1.0350x over previous
#include <cuda_runtime.h>
#include <cuda_bf16.h>
#include <cuda_fp16.h>
#include <cstdint>

#define BB   4
#define NQ   512
#define NK   512
#define DD   512
#define HH   128

#define TQ   8
#define TK   32
#define HPAD 132

// ---------------- scratch (allocation-free device globals) ----------------
__device__ float  g_Qp[BB * NQ * HH];
__device__ float  g_Kp[BB * NK * HH];
__device__ __half g_Qf[BB * NQ * DD];
__device__ __half g_Kf[BB * NK * DD];
__device__ __half g_Wqt[HH * DD];            // W^T [128][512]
__device__ __half g_Wkt[HH * DD];
__device__ __half g_Vt[BB * DD * NK];        // V^T per batch [n][k]
__device__ __half g_Pf[BB * NQ * NK];

__device__ __forceinline__ float fast_tanh(float x) {
    float y;
    asm("tanh.approx.f32 %0, %1;" : "=f"(y) : "f"(x));
    return y;
}

__device__ __forceinline__ long long read_vlen(const void* p, int b) {
    const int* w = (const int*)p;
    bool is64 = (w[1] == 0) && (w[3] == 0);
    if (is64) return ((const long long*)p)[b];
    return (long long)w[b];
}

__device__ __forceinline__ uint32_t smem_u32(const void* p) {
    uint32_t a;
    asm("{ .reg .u64 t; cvta.to.shared.u64 t, %1; cvt.u32.u64 %0, t; }" : "=r"(a) : "l"(p));
    return a;
}

__device__ __forceinline__ void ldmx4(uint32_t* r, uint32_t addr) {
    asm volatile("ldmatrix.sync.aligned.m8n8.x4.shared.b16 {%0,%1,%2,%3}, [%4];"
        : "=r"(r[0]), "=r"(r[1]), "=r"(r[2]), "=r"(r[3]) : "r"(addr));
}

__device__ __forceinline__ void mma16816h(float* d, const uint32_t* a, const uint32_t* b) {
    asm volatile("mma.sync.aligned.m16n8k16.row.col.f32.f16.f16.f32 "
        "{%0,%1,%2,%3}, {%4,%5,%6,%7}, {%8,%9}, {%0,%1,%2,%3};"
        : "+f"(d[0]), "+f"(d[1]), "+f"(d[2]), "+f"(d[3])
        : "r"(a[0]), "r"(a[1]), "r"(a[2]), "r"(a[3]), "r"(b[0]), "r"(b[1]));
}

__device__ __forceinline__ void cpa16(uint32_t dst, const void* src) {
    asm volatile("cp.async.cg.shared.global [%0], [%1], 16;" :: "r"(dst), "l"(src));
}
#define CP_COMMIT() asm volatile("cp.async.commit_group;" ::: "memory")

// ---------------- merged prep kernel (fp16 convert + transposes) ----------
__global__ __launch_bounds__(256)
void prep(const float* __restrict__ Q, const float* __restrict__ K,
          const float* __restrict__ V, const float* __restrict__ Wq,
          const float* __restrict__ Wk, const void* __restrict__ vlen)
{
    __shared__ float t[32][33];
    const int tid = threadIdx.x;
    const int bid = blockIdx.x;

    if (bid < 2048) {
        const bool isK = bid >= 1024;
        const float* in = isK ? K : Q;
        __half* o = isK ? g_Kf : g_Qf;
        int i = (bid & 1023) * 256 + tid;
        float4 v = ((const float4*)in)[i];
        ((__half2*)o)[i * 2 + 0] = __floats2half2_rn(v.x, v.y);
        ((__half2*)o)[i * 2 + 1] = __floats2half2_rn(v.z, v.w);
    } else if (bid < 2560) {
        const int r = bid - 2048;
        const bool isK = r >= 256;
        const float* W = isK ? Wk : Wq;
        __half* th = isK ? g_Wkt : g_Wqt;
        int i = (r & 255) * 256 + tid;
        int k = i >> 7, n = i & 127;
        th[n * DD + k] = __float2half(W[i]);
    } else {
        const int r  = bid - 2560;
        const int b  = r >> 8;
        const int ky = (r & 255) >> 4;
        const int nx = r & 15;
        const int k0 = ky * 32;
        if ((long long)k0 >= read_vlen(vlen, b)) return;
        const int n0 = nx * 32;
        const int tx = tid & 31, ty = tid >> 5;
        const float* Vb = V + (long long)b * NK * DD;
#pragma unroll
        for (int rr = 0; rr < 4; rr++)
            t[ty + rr * 8][tx] = Vb[(long long)(k0 + ty + rr * 8) * DD + n0 + tx];
        __syncthreads();
        __half* th = g_Vt + (long long)b * DD * NK;
#pragma unroll
        for (int rr = 0; rr < 4; rr++)
            th[(long long)(n0 + ty + rr * 8) * NK + k0 + tx] = __float2half(t[tx][ty + rr * 8]);
    }
}

// ---------------- warp-MMA fp16 GEMM: C[64x64] = A[64xK] @ B[64xK]^T ------
// 256 threads = 8 warps (4m x 2n), warp tile 16x32. 80B-padded rows.
// 4-stage cp.async ring (40KB dynamic smem) -> 3 CTAs/SM.
#define STG  10240
#define O_A  0
#define O_B  5120
#define NSTG 4
#define MMA_DSMEM (NSTG * STG)

__device__ __forceinline__ void mma_gemm(
    const __half* __restrict__ A, const __half* __restrict__ B,
    float* __restrict__ C, int lda, int ldb, int ldc,
    int m0, int n0, int nstages)
{
    extern __shared__ __align__(128) char smem[];
    const uint32_t sb = smem_u32(smem);
    const int tid  = threadIdx.x;
    const int lane = tid & 31;
    const int w    = tid >> 5;
    const int wm   = w & 3;
    const int wn   = w >> 2;

    const int lrow = tid >> 2;
    const int lchk = tid & 3;
    const __half* pA = A + (long long)(m0 + lrow) * lda + lchk * 8;
    const __half* pB = B + (long long)(n0 + lrow) * ldb + lchk * 8;
    const uint32_t stO = lrow * 80 + lchk * 16;

    const uint32_t aOff = (wm * 16 + (lane & 15)) * 80 + (lane >> 4) * 16;
    const int jj = lane >> 3;
    const uint32_t bOff = (wn * 32 + (jj >> 1) * 8 + (lane & 7)) * 80 + (jj & 1) * 16;

    float acc[4][4] = {};

    // prologue: stages 0..NSTG-2
#pragma unroll
    for (int s = 0; s < NSTG - 1; s++) {
        if (s < nstages) {
            uint32_t d = sb + s * STG + stO;
            cpa16(d + O_A, pA + s * 32);
            cpa16(d + O_B, pB + s * 32);
        }
        CP_COMMIT();
    }

    for (int t = 0; t < nstages; t++) {
        asm volatile("cp.async.wait_group %0;" :: "n"(NSTG - 2) : "memory");
        __syncthreads();

        {
            int s = t + NSTG - 1;
            if (s < nstages) {
                uint32_t d = sb + (uint32_t)(s & (NSTG - 1)) * STG + stO;
                cpa16(d + O_A, pA + s * 32);
                cpa16(d + O_B, pB + s * 32);
            }
            CP_COMMIT();
        }

        const uint32_t cur = sb + (uint32_t)(t & (NSTG - 1)) * STG;
#pragma unroll
        for (int ks = 0; ks < 2; ks++) {
            uint32_t a[4];
            ldmx4(a, cur + O_A + aOff + ks * 32);
#pragma unroll
            for (int np = 0; np < 2; np++) {
                uint32_t b[4];
                ldmx4(b, cur + O_B + bOff + np * 1280 + ks * 32);
                mma16816h(acc[2 * np + 0], a, b);
                mma16816h(acc[2 * np + 1], a, b + 2);
            }
        }
    }

    const int rr = m0 + wm * 16 + (lane >> 2);
    const int cc = n0 + wn * 32 + (lane & 3) * 2;
#pragma unroll
    for (int nt = 0; nt < 4; nt++) {
        *(float2*)&C[(long long)rr * ldc + cc + nt * 8]       = make_float2(acc[nt][0], acc[nt][1]);
        *(float2*)&C[(long long)(rr + 8) * ldc + cc + nt * 8] = make_float2(acc[nt][2], acc[nt][3]);
    }
}

// z=0: Qp = Q@Wq; z=1: Kp = K@Wk (skip fully-masked row blocks)
__global__ __launch_bounds__(256, 3)
void mma_proj(const void* __restrict__ vlen)
{
    const int n0 = blockIdx.x * 64;
    const int m0 = blockIdx.y * 64;
    if (blockIdx.z == 0) {
        mma_gemm(g_Qf, g_Wqt, g_Qp, DD, DD, HH, m0, n0, DD / 32);
    } else {
        if ((long long)(m0 & (NK - 1)) >= read_vlen(vlen, m0 >> 9)) return;
        mma_gemm(g_Kf, g_Wkt, g_Kp, DD, DD, HH, m0, n0, DD / 32);
    }
}

// out[b] = P[b] @ V[b]; K-loop bounded by valid length (P==0 beyond vl).
__global__ __launch_bounds__(256, 3)
void mma_pv(float* __restrict__ out, const void* __restrict__ vlen)
{
    const int b = blockIdx.z;
    const long long vl = read_vlen(vlen, b);
    const int ns = (int)((vl + 31) >> 5);
    mma_gemm(g_Pf + (long long)b * NQ * NK,
             g_Vt + (long long)b * DD * NK,
             out + (long long)b * NQ * DD,
             NK, NK, DD, blockIdx.y * 64, blockIdx.x * 64, ns);
}

// ---------------- fused scores + mask + softmax -> P (fp16) ----------------
__global__ __launch_bounds__(256)
void scores_softmax(const float* __restrict__ Qp, const float* __restrict__ Kp,
                    const float* __restrict__ wv, const void* __restrict__ vlen)
{
    __shared__ float qps[TQ][HPAD];
    __shared__ float kps[2][TK][HPAD];
    __shared__ float wvs[HH];
    __shared__ float s[TQ][NK];

    const int tid = threadIdx.x;
    const int bx  = blockIdx.x;
    const int b   = bx / (NQ / TQ);
    const int q0  = (bx % (NQ / TQ)) * TQ;

    const long long vl = read_vlen(vlen, b);
    const int NT = (int)((vl + TK - 1) / TK);

    if (tid < HH) wvs[tid] = wv[tid];

    {
        const int q  = tid >> 5;
        const int h4 = (tid & 31) * 4;
        float4 v = *(const float4*)&Qp[(long long)(b * NQ + q0 + q) * HH + h4];
        *(float4*)&qps[q][h4] = v;
    }

    const int q = tid >> 5;
    const int k = tid & 31;

    const float* kbase = &Kp[(long long)b * NK * HH];
    const int lrow = tid >> 5;
    const int lh4  = (tid & 31) * 4;

#pragma unroll
    for (int r = 0; r < 4; r++) {
        int kk = lrow + 8 * r;
        float4 v = *(const float4*)&kbase[(long long)kk * HH + lh4];
        *(float4*)&kps[0][kk][lh4] = v;
    }
    __syncthreads();

    for (int kt = 0; kt < NT; kt++) {
        const int cur = kt & 1;
        const int nxt = cur ^ 1;
        float4 pre[4];
        const bool more = (kt + 1 < NT);
        if (more) {
#pragma unroll
            for (int r = 0; r < 4; r++) {
                int kk = lrow + 8 * r;
                pre[r] = *(const float4*)&kbase[(long long)((kt + 1) * TK + kk) * HH + lh4];
            }
        }

        float acc = 0.f;
#pragma unroll 8
        for (int h4 = 0; h4 < HH / 4; h4++) {
            float4 kv = *(const float4*)&kps[cur][k][h4 * 4];
            float4 qv = *(const float4*)&qps[q][h4 * 4];
            float4 w  = *(const float4*)&wvs[h4 * 4];
            acc += w.x * fast_tanh(qv.x + kv.x);
            acc += w.y * fast_tanh(qv.y + kv.y);
            acc += w.z * fast_tanh(qv.z + kv.z);
            acc += w.w * fast_tanh(qv.w + kv.w);
        }
        s[q][kt * TK + k] = acc;

        if (more) {
#pragma unroll
            for (int r = 0; r < 4; r++) {
                int kk = lrow + 8 * r;
                *(float4*)&kps[nxt][kk][lh4] = pre[r];
            }
        }
        __syncthreads();
    }

    const int lane = k;
    const int kmax = NT * TK;

    float m = -1e30f;
    for (int j = lane; j < kmax; j += 32) {
        float x = (j < vl) ? s[q][j] : -1e30f;
        m = fmaxf(m, x);
    }
#pragma unroll
    for (int o = 16; o > 0; o >>= 1) m = fmaxf(m, __shfl_xor_sync(0xffffffffu, m, o));

    float sum = 0.f;
    for (int j = lane; j < kmax; j += 32) {
        float e = (j < vl) ? __expf(s[q][j] - m) : 0.f;
        s[q][j] = e;
        sum += e;
    }
#pragma unroll
    for (int o = 16; o > 0; o >>= 1) sum += __shfl_xor_sync(0xffffffffu, sum, o);

    const float inv = 1.f / sum;
    __half* pf = g_Pf + (long long)(b * NQ + q0 + q) * NK;
    for (int j = lane; j < kmax; j += 32) {
        float x = (j < vl) ? s[q][j] * inv : 0.f;
        pf[j] = __float2half(x);
    }
}

// ---------------------------------------------------------------------------
extern "C" void kernel_launch(void* const* d_in, const int* in_sizes, int n_in,
                              void* d_out, int out_size)
{
    const float* Q    = (const float*)d_in[0];
    const float* K    = (const float*)d_in[1];
    const float* V    = (const float*)d_in[2];
    const float* Wq   = (const float*)d_in[3];
    const float* Wk   = (const float*)d_in[4];
    const float* wv   = (const float*)d_in[5];
    const void*  vlen = (const void*)d_in[6];
    float*       out  = (float*)d_out;

    float *pQp, *pKp;
    cudaGetSymbolAddress((void**)&pQp, g_Qp);
    cudaGetSymbolAddress((void**)&pKp, g_Kp);

    static bool attr_done = false;
    if (!attr_done) {
        cudaFuncSetAttribute(mma_proj, cudaFuncAttributeMaxDynamicSharedMemorySize, MMA_DSMEM);
        cudaFuncSetAttribute(mma_pv,   cudaFuncAttributeMaxDynamicSharedMemorySize, MMA_DSMEM);
        attr_done = true;
    }

    // prep: fp16 converts + transposes, single launch
    prep<<<3584, 256>>>(Q, K, V, Wq, Wk, vlen);

    // projections: grid (2, 32, 2) = 128 CTAs, 64x64 tiles, 16 k-stages
    {
        dim3 g(HH / 64, (BB * NQ) / 64, 2);
        mma_proj<<<g, 256, MMA_DSMEM>>>(vlen);
    }
    // scores + mask + softmax -> P (fp16)
    {
        dim3 g(BB * NQ / TQ);
        scores_softmax<<<g, 256>>>(pQp, pKp, wv, vlen);
    }
    // out = P @ V: grid (8, 8, 4) = 256 CTAs, <=16 k-stages
    {
        dim3 g(DD / 64, NQ / 64, BB);
        mma_pv<<<g, 256, MMA_DSMEM>>>(out, vlen);
    }
}